// round 17
// baseline (speedup 1.0000x reference)
#include <cuda_runtime.h>
#include <cuda_fp16.h>
#include <cstdint>

// Shape: N=100000, E=1600000, F_in=32, F_out=64, K=3 hops.
#define NMAX 131072
#define EMAX 1703936
#define FIN  32
#define FOUT 64
#define SB   256   // scan tiles

// Static scratch. Referenced ONLY inside device code.
// State z = dinv .* h in fp16: z'[d] = dinv[d]^2 (z[d]+Σz[s]).
__device__ __align__(16) unsigned int g_z16[2][(size_t)NMAX * FIN / 2];
__device__ __align__(128) float g_hf[(size_t)NMAX * FIN];   // final-hop fp32 h
__device__ int   g_cnt[NMAX];        // in-degree (zero-restored each run)
__device__ float g_dinv[NMAX];       // rsqrt(deg incl. self-loop)
__device__ int   g_rowptr[NMAX + 1]; // CSR row pointers (by dst)
__device__ int   g_cursor[NMAX];     // placement cursors
__device__ __align__(16) int g_csr[EMAX]; // CSR: src index only
__device__ int   g_bsum[SB];         // per-tile sums

// ---------------------------------------------------------------------------
// Count in-degree, 4 edges/thread via int4 (1 load + 4 REDs per 4 edges).
__global__ void k_count4(const int* __restrict__ ei, int E4, int E, int N) {
    int g = blockIdx.x * blockDim.x + threadIdx.x;
    if (g < E4) {
        int4 d4 = __ldg((const int4*)(ei + E) + g);
        if ((unsigned)d4.x < (unsigned)N) atomicAdd(&g_cnt[d4.x], 1);
        if ((unsigned)d4.y < (unsigned)N) atomicAdd(&g_cnt[d4.y], 1);
        if ((unsigned)d4.z < (unsigned)N) atomicAdd(&g_cnt[d4.z], 1);
        if ((unsigned)d4.w < (unsigned)N) atomicAdd(&g_cnt[d4.w], 1);
    }
}
__global__ void k_count1(const int* __restrict__ ei, int beg, int E, int N) {
    int e = beg + blockIdx.x * blockDim.x + threadIdx.x;
    if (e < E) {
        int d = ei[E + e];
        if ((unsigned)d < (unsigned)N) atomicAdd(&g_cnt[d], 1);
    }
}

// Scan phase A: tile tree-reduction -> g_bsum; dinv fused.
__global__ void k_scan_a(int N) {
    __shared__ int sh[256];
    int b = blockIdx.x, t = threadIdx.x;
    int tile = (N + SB - 1) / SB;
    int beg = b * tile, end = min(beg + tile, N);
    int s = 0;
    for (int i = beg + t; i < end; i += 256) {
        int c = g_cnt[i];
        s += c;
        g_dinv[i] = rsqrtf((float)(c + 1));
    }
    sh[t] = s;
    __syncthreads();
#pragma unroll
    for (int off = 128; off > 0; off >>= 1) {
        if (t < off) sh[t] += sh[t + off];
        __syncthreads();
    }
    if (t == 0) g_bsum[b] = sh[0];
}

// Scan phase C (fused B): block offset via redundant smem scan of tile sums,
// local scan into rowptr/cursor, zero-restore g_cnt.
__global__ void k_scan_c(int N) {
    __shared__ int shB[SB];
    __shared__ int sh[256];
    int b = blockIdx.x, t = threadIdx.x;

    int v = g_bsum[t];
    shB[t] = v;
    __syncthreads();
#pragma unroll
    for (int off = 1; off < SB; off <<= 1) {
        int u = (t >= off) ? shB[t - off] : 0;
        __syncthreads();
        shB[t] += u;
        __syncthreads();
    }
    if (b == SB - 1 && t == 0) g_rowptr[N] = shB[SB - 1];
    int blockOff = (b == 0) ? 0 : shB[b - 1];

    int tile = (N + SB - 1) / SB;
    int beg = b * tile, end = min(beg + tile, N);
    int chunk = (tile + 255) / 256;
    int cbeg = beg + t * chunk;
    int cend = min(cbeg + chunk, end);
    int s = 0;
    for (int i = cbeg; i < cend; i++) s += g_cnt[i];
    sh[t] = s;
    __syncthreads();
#pragma unroll
    for (int off = 1; off < 256; off <<= 1) {
        int u = (t >= off) ? sh[t - off] : 0;
        __syncthreads();
        sh[t] += u;
        __syncthreads();
    }
    int run = blockOff + sh[t] - s;
    for (int i = cbeg; i < cend; i++) {
        g_rowptr[i] = run;
        g_cursor[i] = run;
        run += g_cnt[i];
        g_cnt[i] = 0;
    }
}

// Place edges into CSR, 4 edges/thread via int4 loads.
__global__ void k_place4(const int* __restrict__ ei, int E4, int E, int N) {
    int g = blockIdx.x * blockDim.x + threadIdx.x;
    if (g < E4) {
        int4 s4 = __ldg((const int4*)ei + g);
        int4 d4 = __ldg((const int4*)(ei + E) + g);
        if ((unsigned)s4.x < (unsigned)N && (unsigned)d4.x < (unsigned)N)
            g_csr[atomicAdd(&g_cursor[d4.x], 1)] = s4.x;
        if ((unsigned)s4.y < (unsigned)N && (unsigned)d4.y < (unsigned)N)
            g_csr[atomicAdd(&g_cursor[d4.y], 1)] = s4.y;
        if ((unsigned)s4.z < (unsigned)N && (unsigned)d4.z < (unsigned)N)
            g_csr[atomicAdd(&g_cursor[d4.z], 1)] = s4.z;
        if ((unsigned)s4.w < (unsigned)N && (unsigned)d4.w < (unsigned)N)
            g_csr[atomicAdd(&g_cursor[d4.w], 1)] = s4.w;
    }
}
__global__ void k_place1(const int* __restrict__ ei, int beg, int E, int N) {
    int e = beg + blockIdx.x * blockDim.x + threadIdx.x;
    if (e < E) {
        int s = ei[e];
        int d = ei[E + e];
        if ((unsigned)s < (unsigned)N && (unsigned)d < (unsigned)N)
            g_csr[atomicAdd(&g_cursor[d], 1)] = s;
    }
}

// One-time convert: z0 = dinv[n] * x[n][:]  (fp32 -> scaled fp16).
__global__ void k_conv(const float2* __restrict__ x, int N) {
    int t = blockIdx.x * blockDim.x + threadIdx.x;
    int n2 = N * (FIN / 2);
    if (t < n2) {
        int n = t >> 4;                 // FIN/2 == 16 half2 per row
        float dv = g_dinv[n];
        float2 v = __ldg(&x[t]);
        ((__half2*)g_z16[0])[t] = __floats2half2_rn(dv * v.x, dv * v.y);
    }
}

// Accumulate one gathered row-slice (8 halfs) into 8 fp32 registers.
__device__ __forceinline__ void acc8(const uint4* in, int s, int j,
                                     float& r0, float& r1, float& r2, float& r3,
                                     float& r4, float& r5, float& r6, float& r7) {
    uint4 v = __ldg(&in[(size_t)s * 4 + j]);
    float2 q0 = __half22float2(*(__half2*)&v.x);
    float2 q1 = __half22float2(*(__half2*)&v.y);
    float2 q2 = __half22float2(*(__half2*)&v.z);
    float2 q3 = __half22float2(*(__half2*)&v.w);
    r0 += q0.x; r1 += q0.y; r2 += q1.x; r3 += q1.y;
    r4 += q2.x; r5 += q2.y; r6 += q3.x; r7 += q3.y;
}

// fp16 z-hop: z'[d][:] = dinv[d]^2 * (z[d][:] + Σ z[src_e][:]).
// 4 lanes per dst row; CSR consumed as aligned int4 blocks (broadcast load).
__global__ void k_hop16(int srcSel, int dstSel, int N) {
    const uint4* in  = (const uint4*)g_z16[srcSel];
    uint4*       out = (uint4*)g_z16[dstSel];
    int t = blockIdx.x * blockDim.x + threadIdx.x;
    int d = t >> 2;
    int j = t & 3;
    if (d >= N) return;

    uint4 a = __ldg(&in[(size_t)d * 4 + j]);
    float2 p0 = __half22float2(*(__half2*)&a.x);
    float2 p1 = __half22float2(*(__half2*)&a.y);
    float2 p2 = __half22float2(*(__half2*)&a.z);
    float2 p3 = __half22float2(*(__half2*)&a.w);
    float r0 = p0.x, r1 = p0.y, r2 = p1.x, r3 = p1.y;
    float r4 = p2.x, r5 = p2.y, r6 = p3.x, r7 = p3.y;

    int beg = g_rowptr[d];
    int end = g_rowptr[d + 1];
    int i = beg;
    int aend = min(end, (beg + 3) & ~3);     // scalar until 16B-aligned
    for (; i < aend; i++)
        acc8(in, __ldg(&g_csr[i]), j, r0, r1, r2, r3, r4, r5, r6, r7);
    for (; i + 4 <= end; i += 4) {
        int4 s4 = __ldg((const int4*)&g_csr[i]);   // one broadcast load / 4 edges
        acc8(in, s4.x, j, r0, r1, r2, r3, r4, r5, r6, r7);
        acc8(in, s4.y, j, r0, r1, r2, r3, r4, r5, r6, r7);
        acc8(in, s4.z, j, r0, r1, r2, r3, r4, r5, r6, r7);
        acc8(in, s4.w, j, r0, r1, r2, r3, r4, r5, r6, r7);
    }
    for (; i < end; i++)
        acc8(in, __ldg(&g_csr[i]), j, r0, r1, r2, r3, r4, r5, r6, r7);

    float dv = g_dinv[d];
    float c = dv * dv;
    __half2 o0 = __floats2half2_rn(c * r0, c * r1);
    __half2 o1 = __floats2half2_rn(c * r2, c * r3);
    __half2 o2 = __floats2half2_rn(c * r4, c * r5);
    __half2 o3 = __floats2half2_rn(c * r6, c * r7);
    uint4 o;
    o.x = *(unsigned int*)&o0; o.y = *(unsigned int*)&o1;
    o.z = *(unsigned int*)&o2; o.w = *(unsigned int*)&o3;
    out[(size_t)d * 4 + j] = o;
}

// Final hop: h3[d][:] = dinv[d] * (z[d][:] + Σ z[src_e][:]) -> fp32 g_hf.
__global__ void k_hop16f(int srcSel, int N) {
    const uint4* in = (const uint4*)g_z16[srcSel];
    int t = blockIdx.x * blockDim.x + threadIdx.x;
    int d = t >> 2;
    int j = t & 3;
    if (d >= N) return;

    uint4 a = __ldg(&in[(size_t)d * 4 + j]);
    float2 p0 = __half22float2(*(__half2*)&a.x);
    float2 p1 = __half22float2(*(__half2*)&a.y);
    float2 p2 = __half22float2(*(__half2*)&a.z);
    float2 p3 = __half22float2(*(__half2*)&a.w);
    float r0 = p0.x, r1 = p0.y, r2 = p1.x, r3 = p1.y;
    float r4 = p2.x, r5 = p2.y, r6 = p3.x, r7 = p3.y;

    int beg = g_rowptr[d];
    int end = g_rowptr[d + 1];
    int i = beg;
    int aend = min(end, (beg + 3) & ~3);
    for (; i < aend; i++)
        acc8(in, __ldg(&g_csr[i]), j, r0, r1, r2, r3, r4, r5, r6, r7);
    for (; i + 4 <= end; i += 4) {
        int4 s4 = __ldg((const int4*)&g_csr[i]);
        acc8(in, s4.x, j, r0, r1, r2, r3, r4, r5, r6, r7);
        acc8(in, s4.y, j, r0, r1, r2, r3, r4, r5, r6, r7);
        acc8(in, s4.z, j, r0, r1, r2, r3, r4, r5, r6, r7);
        acc8(in, s4.w, j, r0, r1, r2, r3, r4, r5, r6, r7);
    }
    for (; i < end; i++)
        acc8(in, __ldg(&g_csr[i]), j, r0, r1, r2, r3, r4, r5, r6, r7);

    float dv = g_dinv[d];
    float4* out = (float4*)g_hf;
    out[(size_t)d * 8 + 2 * j + 0] = make_float4(dv * r0, dv * r1, dv * r2, dv * r3);
    out[(size_t)d * 8 + 2 * j + 1] = make_float4(dv * r4, dv * r5, dv * r6, dv * r7);
}

// Warp-shuffle GEMM: lane l holds W[l][:] and W[l+32][:] in registers.
__global__ void k_gemm(const float* __restrict__ W,
                       const float* __restrict__ b, float* __restrict__ out, int N) {
    const float* h = g_hf;
    int lane = threadIdx.x & 31;
    int warp = (blockIdx.x * blockDim.x + threadIdx.x) >> 5;
    int nwarps = (gridDim.x * blockDim.x) >> 5;

    float w0[FIN], w1[FIN];
    const float4* Wv = (const float4*)W;
#pragma unroll
    for (int k4 = 0; k4 < FIN / 4; k4++) {
        float4 u = __ldg(&Wv[lane * (FIN / 4) + k4]);
        w0[4 * k4 + 0] = u.x; w0[4 * k4 + 1] = u.y;
        w0[4 * k4 + 2] = u.z; w0[4 * k4 + 3] = u.w;
        float4 v = __ldg(&Wv[(lane + 32) * (FIN / 4) + k4]);
        w1[4 * k4 + 0] = v.x; w1[4 * k4 + 1] = v.y;
        w1[4 * k4 + 2] = v.z; w1[4 * k4 + 3] = v.w;
    }
    float b0 = __ldg(&b[lane]);
    float b1 = __ldg(&b[lane + 32]);

    for (int n = warp; n < N; n += nwarps) {
        float xv = h[(size_t)n * FIN + lane];
        float a0 = b0, a1 = b1;
#pragma unroll
        for (int k = 0; k < FIN; k++) {
            float xk = __shfl_sync(0xffffffffu, xv, k);
            a0 += xk * w0[k];
            a1 += xk * w1[k];
        }
        out[(size_t)n * FOUT + lane] = a0;
        out[(size_t)n * FOUT + 32 + lane] = a1;
    }
}

// ---------------------------------------------------------------------------
extern "C" void kernel_launch(void* const* d_in, const int* in_sizes, int n_in,
                              void* d_out, int out_size) {
    const float* x  = (const float*)d_in[0];   // [N, 32] f32
    const int*   ei = (const int*)d_in[1];     // [2, E] int32
    const float* W  = (const float*)d_in[2];   // [64, 32] f32
    const float* b  = (const float*)d_in[3];   // [64] f32
    float*       out = (float*)d_out;          // [N, 64] f32

    const int N = in_sizes[0] / FIN;
    const int E = in_sizes[1] / 2;

    const int TB = 256;

    // --- CSR build (vectorized x4 when the dst half is 16B-aligned) ---
    if ((E & 3) == 0) {
        const int E4 = E >> 2;
        const int nB4 = (E4 + TB - 1) / TB;
        k_count4<<<nB4, TB>>>(ei, E4, E, N);
        k_scan_a<<<SB, 256>>>(N);
        k_scan_c<<<SB, 256>>>(N);
        k_place4<<<nB4, TB>>>(ei, E4, E, N);
    } else {
        const int nBE = (E + TB - 1) / TB;
        k_count1<<<nBE, TB>>>(ei, 0, E, N);
        k_scan_a<<<SB, 256>>>(N);
        k_scan_c<<<SB, 256>>>(N);
        k_place1<<<nBE, TB>>>(ei, 0, E, N);
    }

    // --- z0 = dinv .* x (fp16), then K=3 hops in z-space ---
    const int n2 = N * (FIN / 2);
    k_conv<<<(n2 + TB - 1) / TB, TB>>>((const float2*)x, N);

    const int hopThreads = N * 4;
    const int hopBlocks = (hopThreads + TB - 1) / TB;
    k_hop16 <<<hopBlocks, TB>>>(0, 1, N);   // z0 -> z1
    k_hop16 <<<hopBlocks, TB>>>(1, 0, N);   // z1 -> z2
    k_hop16f<<<hopBlocks, TB>>>(0, N);      // z2 -> h3 (fp32)

    // --- final linear transform ---
    k_gemm<<<1536, TB>>>(W, b, out, N);
}